// round 4
// baseline (speedup 1.0000x reference)
#include <cuda_runtime.h>
#include <cuda_fp16.h>
#include <cstddef>
#include <cstdint>

// ---------------- problem constants ----------------
#define Bsz   32
#define CINc  16
#define Hh    32
#define Ww    128
#define Oc    128
#define NTOT  512          // 128 channels x 4 gates, interleaved n = ch*4 + gate
#define KTOT  144          // 128 (h) + 16 (x)
#define ASTR  168          // padded half-stride
#define BSTR  168

// ---------------- shared memory layout (bytes) ----------------
#define OFF_B     0
#define SZ_B      (NTOT * BSTR * 2)            // 172032
#define OFF_A     (OFF_B + SZ_B)               // 172032
#define SZ_A      (64 * ASTR * 2)              // 21504
#define OFF_CL    (OFF_A + SZ_A)               // 193536
#define SZ_CL     (Bsz * Oc * 4)               // 16384
#define OFF_BIAS  (OFF_CL + SZ_CL)             // 209920
#define SZ_BIAS   (5 * Oc * 4)                 // 2560
#define SMEM_TOTAL (OFF_BIAS + SZ_BIAS)        // 212480

// transpose tile stride (halves); 69 words odd -> conflict-free strided reads
#define TTS 138

// ---------------- global scratch ----------------
// [bid][w][b][ch] with bid = d*32 + r  (direction-frame row)
__device__ __align__(256) __half  g_hbuf[(size_t)128 * 128 * 32 * 128];
__device__ __align__(256) float   g_cbuf[(size_t)128 * 128 * 32 * 128];
__device__ unsigned               g_progress[128];

// ---------------- helpers ----------------
__device__ __forceinline__ float tnhf(float x) {
    float y;
    asm("tanh.approx.f32 %0, %1;" : "=f"(y) : "f"(x));
    return y;
}
__device__ __forceinline__ float sigf(float x) {
    return fmaf(tnhf(0.5f * x), 0.5f, 0.5f);
}
__device__ __forceinline__ unsigned ld_acq(const unsigned* p) {
    unsigned v;
    asm volatile("ld.acquire.gpu.global.b32 %0, [%1];" : "=r"(v) : "l"(p));
    return v;
}
__device__ __forceinline__ void st_rel(unsigned* p, unsigned v) {
    asm volatile("st.release.gpu.global.b32 [%0], %1;" :: "l"(p), "r"(v) : "memory");
}
__device__ __forceinline__ void mma16816(float* c, const unsigned* a, unsigned b0, unsigned b1) {
    asm volatile(
        "mma.sync.aligned.m16n8k16.row.col.f32.f16.f16.f32 "
        "{%0,%1,%2,%3}, {%4,%5,%6,%7}, {%8,%9}, {%0,%1,%2,%3};"
        : "+f"(c[0]), "+f"(c[1]), "+f"(c[2]), "+f"(c[3])
        : "r"(a[0]), "r"(a[1]), "r"(a[2]), "r"(a[3]), "r"(b0), "r"(b1));
}
__device__ __forceinline__ unsigned lds_u32(const __half* p) {
    return *reinterpret_cast<const unsigned*>(p);
}

__global__ void init_progress_kernel() {
    if (threadIdx.x < 128) g_progress[threadIdx.x] = 0u;
}

// ---------------- main persistent kernel: one CTA per (direction, row) ----------------
__global__ void __launch_bounds__(256, 1) mdlstm_kernel(
    const float* __restrict__ x,
    const float* __restrict__ w_ii, const float* __restrict__ w_hi, const float* __restrict__ b_i,
    const float* __restrict__ w_if, const float* __restrict__ w_hf, const float* __restrict__ b_f,
    const float* __restrict__ w_ig, const float* __restrict__ w_hg, const float* __restrict__ b_g,
    const float* __restrict__ w_io, const float* __restrict__ w_ho, const float* __restrict__ b_o,
    const float* __restrict__ wsum, const float* __restrict__ biasv,
    float* __restrict__ out)
{
    extern __shared__ char smem[];
    __half* sB    = reinterpret_cast<__half*>(smem + OFF_B);
    __half* sA    = reinterpret_cast<__half*>(smem + OFF_A);
    float*  sCl   = reinterpret_cast<float*>(smem + OFF_CL);
    float*  sBias = reinterpret_cast<float*>(smem + OFF_BIAS);

    const int tid  = threadIdx.x;
    const int lane = tid & 31;
    const int wid  = tid >> 5;
    const int bid  = blockIdx.x;
    const int d    = bid >> 5;
    const int r    = bid & 31;
    const bool fx  = (d & 1) != 0;
    const bool fy  = (d & 2) != 0;
    const int  ph  = fy ? (Hh - 1 - r) : r;

    // ---- stage weights: sB[n][k], n = ch*4 + gate, k = 0..127 (Wh) | 128..143 (Wi) ----
    {
        const float* whArr[4] = {w_hi, w_hf, w_hg, w_ho};
        const float* wiArr[4] = {w_ii, w_if, w_ig, w_io};
        for (int gate = 0; gate < 4; ++gate) {
            const float* wh = whArr[gate] + (size_t)d * Oc * Oc;
            for (int idx = tid; idx < Oc * Oc; idx += 256) {
                int ch = idx >> 7, k = idx & 127;
                sB[(ch * 4 + gate) * BSTR + k] = __float2half(wh[idx]);
            }
            const float* wi = wiArr[gate] + (size_t)d * Oc * CINc;
            for (int idx = tid; idx < Oc * CINc; idx += 256) {
                int ch = idx >> 4, k = idx & 15;
                sB[(ch * 4 + gate) * BSTR + 128 + k] = __float2half(wi[idx]);
            }
        }
        const float* bArr[4] = {b_i, b_f, b_g, b_o};
        for (int idx = tid; idx < 512; idx += 256)
            sBias[idx] = bArr[idx >> 7][(size_t)d * Oc + (idx & 127)];
        if (tid < 128) sBias[512 + tid] = biasv[(size_t)d * Oc + tid];
        // zero h_left rows (A rows 32..63, cols 0..127) and c_left
        for (int idx = tid; idx < 32 * 128; idx += 256) {
            int b = idx >> 7, c = idx & 127;
            sA[(32 + b) * ASTR + c] = __float2half(0.f);
        }
        for (int idx = tid; idx < Bsz * Oc; idx += 256) sCl[idx] = 0.f;
        if (r == 0) {   // h_top = 0 forever for the first row
            for (int idx = tid; idx < 32 * 128; idx += 256) {
                int b = idx >> 7, c = idx & 127;
                sA[b * ASTR + c] = __float2half(0.f);
            }
        }
    }
    const float ws0 = wsum[d * 2 + 0];
    const float ws1 = wsum[d * 2 + 1];
    __syncthreads();

    const int g = lane >> 2, t = lane & 3;
    const bool oddt = (t & 1) != 0;
    const __half* Abase = sA + g * ASTR + t * 2;
    const __half* Bbase = sB + ((wid << 6) + g) * BSTR + t * 2;

#pragma unroll 1
    for (int w = 0; w < Ww; ++w) {
        const int pw = fx ? (Ww - 1 - w) : w;
        const size_t rowoff = ((size_t)bid * Ww + w) * (Bsz * Oc);
        const size_t topoff = rowoff - (size_t)Ww * (Bsz * Oc);

        // ---- wait for the row above to publish column w ----
        if (r > 0 && tid == 0) {
            while (ld_acq(&g_progress[bid - 1]) <= (unsigned)w) __nanosleep(32);
        }
        __syncthreads();   // S1

        // ---- stage h_top (A rows 0..31) and x (A cols 128..143, both halves) ----
        if (r > 0) {
            const uint4* src = reinterpret_cast<const uint4*>(g_hbuf + topoff);
#pragma unroll
            for (int j = 0; j < 2; ++j) {
                int idx = tid + j * 256;        // uint4 units: 32 rows x 16
                int b = idx >> 4, s = idx & 15;
                *reinterpret_cast<uint4*>(sA + b * ASTR + s * 8) = src[idx];
            }
        }
#pragma unroll
        for (int j = 0; j < 2; ++j) {
            int idx = tid + j * 256;            // b*16 + ci
            int b = idx >> 4, ci = idx & 15;
            __half hx = __float2half(x[(size_t)idx * (Hh * Ww) + ph * Ww + pw]);
            sA[b * ASTR + 128 + ci]        = hx;
            sA[(32 + b) * ASTR + 128 + ci] = hx;
        }
        __syncthreads();   // S2: A ready

        // ---- MMA: C(64x512) += A(64x144) * B(144x512), per warp 64 n-cols ----
        float acc[4][8][4];
#pragma unroll
        for (int mt = 0; mt < 4; ++mt)
#pragma unroll
            for (int nt = 0; nt < 8; ++nt)
#pragma unroll
                for (int q = 0; q < 4; ++q) acc[mt][nt][q] = 0.f;

#pragma unroll
        for (int k = 0; k < 9; ++k) {
            unsigned af[4][4];
#pragma unroll
            for (int mt = 0; mt < 4; ++mt) {
                const __half* ap = Abase + mt * 16 * ASTR + k * 16;
                af[mt][0] = lds_u32(ap);
                af[mt][1] = lds_u32(ap + 8 * ASTR);
                af[mt][2] = lds_u32(ap + 8);
                af[mt][3] = lds_u32(ap + 8 * ASTR + 8);
            }
#pragma unroll
            for (int nt = 0; nt < 8; ++nt) {
                const __half* bp = Bbase + nt * 8 * BSTR + k * 16;
                unsigned b0 = lds_u32(bp);
                unsigned b1 = lds_u32(bp + 8);
#pragma unroll
                for (int mt = 0; mt < 4; ++mt)
                    mma16816(acc[mt][nt], af[mt], b0, b1);
            }
        }
        __syncthreads();   // S3: all warps done reading sA before epilogue rewrites h_left

        // ---- epilogue: gates, cell update, publish h/c ----
#pragma unroll
        for (int p = 0; p < 2; ++p) {
#pragma unroll
            for (int nt = 0; nt < 8; ++nt) {
                float* c0 = acc[p][nt];       // branch0 (top):  rows p*16..
                float* c1 = acc[p + 2][nt];   // branch1 (left): rows 32+p*16..
                float rA0 = __shfl_xor_sync(0xffffffffu, oddt ? c0[0] : c0[2], 1);
                float rB0 = __shfl_xor_sync(0xffffffffu, oddt ? c0[1] : c0[3], 1);
                float rA1 = __shfl_xor_sync(0xffffffffu, oddt ? c1[0] : c1[2], 1);
                float rB1 = __shfl_xor_sync(0xffffffffu, oddt ? c1[1] : c1[3], 1);
                float pi0, pf0, pg0, po0, pi1, pf1, pg1, po1;
                if (!oddt) { pi0 = c0[0]; pf0 = c0[1]; pg0 = rA0;  po0 = rB0;
                             pi1 = c1[0]; pf1 = c1[1]; pg1 = rA1;  po1 = rB1; }
                else       { pi0 = rA0;  pf0 = rB0;  pg0 = c0[2]; po0 = c0[3];
                             pi1 = rA1;  pf1 = rB1;  pg1 = c1[2]; po1 = c1[3]; }

                const int bb = p * 16 + g + (oddt ? 8 : 0);
                const int ch = (wid << 4) + nt * 2 + (t >> 1);

                const float bi = sBias[ch],        bf2 = sBias[128 + ch];
                const float bg = sBias[256 + ch],  bo  = sBias[384 + ch];
                const float bv = sBias[512 + ch];

                float ctop = 0.f;
                if (r > 0) ctop = g_cbuf[topoff + bb * Oc + ch];
                const float clft = sCl[bb * Oc + ch];

                const float i0 = sigf(pi0 + bi), f0 = sigf(pf0 + bf2);
                const float g0 = tnhf(pg0 + bg), o0 = sigf(po0 + bo);
                const float cn0 = f0 * ctop + i0 * g0;
                const float h0  = o0 * tnhf(cn0);

                const float i1 = sigf(pi1 + bi), f1 = sigf(pf1 + bf2);
                const float g1 = tnhf(pg1 + bg), o1 = sigf(po1 + bo);
                const float cn1 = f1 * clft + i1 * g1;
                const float h1  = o1 * tnhf(cn1);

                const float ct = ws0 * cn0 + ws1 * cn1 + bv;
                const float ht = ws0 * h0  + ws1 * h1  + bv;

                sCl[bb * Oc + ch] = ct;
                g_cbuf[rowoff + bb * Oc + ch] = ct;
                const __half hh = __float2half(ht);
                sA[(32 + bb) * ASTR + ch] = hh;        // h_left for next column
                g_hbuf[rowoff + bb * Oc + ch] = hh;    // h_top for row below + output
            }
        }
        __syncthreads();   // S4: all writes done before publish
        if (tid == 0) st_rel(&g_progress[bid], (unsigned)(w + 1));
    }

    // ---- output epilogue: transpose f16 row history -> coalesced fp32 stores ----
    // out[d][ch][b][ph][pw] = h[r][w][b][ch], w = fx ? 127-pw : pw
    __half* tile = reinterpret_cast<__half*>(smem);   // reuse sB region (~35 KB)
    float* outp = out + (size_t)d * Oc * Bsz * Hh * Ww;
    __syncthreads();
#pragma unroll 1
    for (int b = 0; b < Bsz; ++b) {
        // stage: tile[w][ch] (FULL 128 ch = 64 u32 per row; fixed off-by-2x)
#pragma unroll 1
        for (int idx = tid; idx < 128 * 64; idx += 256) {      // u32 units: 128 w x 64
            int wq = idx >> 6, s = idx & 63;
            unsigned v = *reinterpret_cast<const unsigned*>(
                g_hbuf + ((size_t)bid * Ww + wq) * (Bsz * Oc) + b * Oc + s * 2);
            *reinterpret_cast<unsigned*>(tile + wq * TTS + s * 2) = v;
        }
        __syncthreads();
#pragma unroll 1
        for (int idx = tid; idx < 128 * 128; idx += 256) {
            int ch = idx >> 7, pw = idx & 127;
            int ww = fx ? (127 - pw) : pw;
            outp[(((size_t)ch * Bsz + b) * Hh + ph) * Ww + pw] =
                __half2float(tile[ww * TTS + ch]);
        }
        __syncthreads();
    }
}

// ---------------- launch ----------------
extern "C" void kernel_launch(void* const* d_in, const int* in_sizes, int n_in,
                              void* d_out, int out_size)
{
    const float* x     = (const float*)d_in[0];
    const float* w_ii  = (const float*)d_in[1];
    const float* w_hi  = (const float*)d_in[2];
    const float* b_i   = (const float*)d_in[3];
    const float* w_if  = (const float*)d_in[4];
    const float* w_hf  = (const float*)d_in[5];
    const float* b_f   = (const float*)d_in[6];
    const float* w_ig  = (const float*)d_in[7];
    const float* w_hg  = (const float*)d_in[8];
    const float* b_g   = (const float*)d_in[9];
    const float* w_io  = (const float*)d_in[10];
    const float* w_ho  = (const float*)d_in[11];
    const float* b_o   = (const float*)d_in[12];
    const float* wsum  = (const float*)d_in[13];
    const float* biasv = (const float*)d_in[14];
    float* out = (float*)d_out;

    cudaFuncSetAttribute(mdlstm_kernel,
                         cudaFuncAttributeMaxDynamicSharedMemorySize, SMEM_TOTAL);

    init_progress_kernel<<<1, 128>>>();
    mdlstm_kernel<<<128, 256, SMEM_TOTAL>>>(
        x, w_ii, w_hi, b_i, w_if, w_hf, b_f, w_ig, w_hg, b_g,
        w_io, w_ho, b_o, wsum, biasv, out);
}

// round 5
// speedup vs baseline: 1.1600x; 1.1600x over previous
#include <cuda_runtime.h>
#include <cuda_fp16.h>
#include <cstddef>
#include <cstdint>

// ---------------- problem constants ----------------
#define Bsz   32
#define CINc  16
#define Hh    32
#define Ww    128
#define Oc    128
#define NTOT  512          // 128 channels x 4 gates, interleaved n = ch*4 + gate
#define KTOT  144          // 128 (h) + 16 (x)
#define ASTR  168          // padded half-stride
#define BSTR  168
#define THREADS 512

// ---------------- shared memory layout (bytes) ----------------
#define OFF_B     0
#define SZ_B      (NTOT * BSTR * 2)            // 172032
#define OFF_A     (OFF_B + SZ_B)               // 172032
#define SZ_A      (64 * ASTR * 2)              // 21504
#define OFF_CL    (OFF_A + SZ_A)               // 193536
#define SZ_CL     (Bsz * Oc * 4)               // 16384
#define OFF_BIAS  (OFF_CL + SZ_CL)             // 209920
#define SZ_BIAS   (5 * Oc * 4)                 // 2560
#define SMEM_TOTAL (OFF_BIAS + SZ_BIAS)        // 212480

// transpose tile stride (halves); 69 words odd -> conflict-free strided reads
#define TTS 138

// ---------------- global scratch ----------------
// [bid][w][b][ch] with bid = d*32 + r  (direction-frame row)
__device__ __align__(256) __half  g_hbuf[(size_t)128 * 128 * 32 * 128];
__device__ __align__(256) float   g_cbuf[(size_t)128 * 128 * 32 * 128];
__device__ unsigned               g_progress[128];

// ---------------- helpers ----------------
__device__ __forceinline__ float tnhf(float x) {
    float y;
    asm("tanh.approx.f32 %0, %1;" : "=f"(y) : "f"(x));
    return y;
}
__device__ __forceinline__ float sigf(float x) {
    return fmaf(tnhf(0.5f * x), 0.5f, 0.5f);
}
__device__ __forceinline__ unsigned ld_acq(const unsigned* p) {
    unsigned v;
    asm volatile("ld.acquire.gpu.global.b32 %0, [%1];" : "=r"(v) : "l"(p));
    return v;
}
__device__ __forceinline__ void st_rel(unsigned* p, unsigned v) {
    asm volatile("st.release.gpu.global.b32 [%0], %1;" :: "l"(p), "r"(v) : "memory");
}
__device__ __forceinline__ void mma16816(float* c, const unsigned* a, unsigned b0, unsigned b1) {
    asm volatile(
        "mma.sync.aligned.m16n8k16.row.col.f32.f16.f16.f32 "
        "{%0,%1,%2,%3}, {%4,%5,%6,%7}, {%8,%9}, {%0,%1,%2,%3};"
        : "+f"(c[0]), "+f"(c[1]), "+f"(c[2]), "+f"(c[3])
        : "r"(a[0]), "r"(a[1]), "r"(a[2]), "r"(a[3]), "r"(b0), "r"(b1));
}
__device__ __forceinline__ unsigned lds_u32(const __half* p) {
    return *reinterpret_cast<const unsigned*>(p);
}

__global__ void init_progress_kernel() {
    if (threadIdx.x < 128) g_progress[threadIdx.x] = 0u;
}

// ---------------- main persistent kernel: one CTA per (direction, row) ----------------
__global__ void __launch_bounds__(THREADS, 1) mdlstm_kernel(
    const float* __restrict__ x,
    const float* __restrict__ w_ii, const float* __restrict__ w_hi, const float* __restrict__ b_i,
    const float* __restrict__ w_if, const float* __restrict__ w_hf, const float* __restrict__ b_f,
    const float* __restrict__ w_ig, const float* __restrict__ w_hg, const float* __restrict__ b_g,
    const float* __restrict__ w_io, const float* __restrict__ w_ho, const float* __restrict__ b_o,
    const float* __restrict__ wsum, const float* __restrict__ biasv,
    float* __restrict__ out)
{
    extern __shared__ char smem[];
    __half* sB    = reinterpret_cast<__half*>(smem + OFF_B);
    __half* sA    = reinterpret_cast<__half*>(smem + OFF_A);
    float*  sCl   = reinterpret_cast<float*>(smem + OFF_CL);
    float*  sBias = reinterpret_cast<float*>(smem + OFF_BIAS);

    const int tid  = threadIdx.x;
    const int lane = tid & 31;
    const int wid  = tid >> 5;          // 0..15
    const int bid  = blockIdx.x;
    const int d    = bid >> 5;
    const int r    = bid & 31;
    const bool fx  = (d & 1) != 0;
    const bool fy  = (d & 2) != 0;
    const int  ph  = fy ? (Hh - 1 - r) : r;

    // ---- stage weights: sB[n][k], n = ch*4 + gate, k = 0..127 (Wh) | 128..143 (Wi) ----
    {
        const float* whArr[4] = {w_hi, w_hf, w_hg, w_ho};
        const float* wiArr[4] = {w_ii, w_if, w_ig, w_io};
        for (int gate = 0; gate < 4; ++gate) {
            const float* wh = whArr[gate] + (size_t)d * Oc * Oc;
            for (int idx = tid; idx < Oc * Oc; idx += THREADS) {
                int ch = idx >> 7, k = idx & 127;
                sB[(ch * 4 + gate) * BSTR + k] = __float2half(wh[idx]);
            }
            const float* wi = wiArr[gate] + (size_t)d * Oc * CINc;
            for (int idx = tid; idx < Oc * CINc; idx += THREADS) {
                int ch = idx >> 4, k = idx & 15;
                sB[(ch * 4 + gate) * BSTR + 128 + k] = __float2half(wi[idx]);
            }
        }
        const float* bArr[4] = {b_i, b_f, b_g, b_o};
        if (tid < 512)
            sBias[tid] = bArr[tid >> 7][(size_t)d * Oc + (tid & 127)];
        if (tid < 128) sBias[512 + tid] = biasv[(size_t)d * Oc + tid];
        // zero h_left rows (A rows 32..63, cols 0..127) and c_left
        for (int idx = tid; idx < 32 * 128; idx += THREADS) {
            int b = idx >> 7, c = idx & 127;
            sA[(32 + b) * ASTR + c] = __float2half(0.f);
        }
        for (int idx = tid; idx < Bsz * Oc; idx += THREADS) sCl[idx] = 0.f;
        if (r == 0) {   // h_top = 0 forever for the first row
            for (int idx = tid; idx < 32 * 128; idx += THREADS) {
                int b = idx >> 7, c = idx & 127;
                sA[b * ASTR + c] = __float2half(0.f);
            }
        }
    }
    const float ws0 = wsum[d * 2 + 0];
    const float ws1 = wsum[d * 2 + 1];
    __syncthreads();

    const int g = lane >> 2, t = lane & 3;
    const bool oddt = (t & 1) != 0;
    const __half* Abase = sA + g * ASTR + t * 2;
    const __half* Bbase = sB + ((wid << 5) + g) * BSTR + t * 2;   // 32 n-cols per warp

    // epilogue ownership (constant per thread)
    const int chB = (wid << 3) + (t >> 1);          // + nt*2
    const int bbB = g + (oddt ? 8 : 0);             // + p*16

#pragma unroll 1
    for (int w = 0; w < Ww; ++w) {
        const int pw = fx ? (Ww - 1 - w) : w;
        const size_t rowoff = ((size_t)bid * Ww + w) * (Bsz * Oc);
        const size_t topoff = rowoff - (size_t)Ww * (Bsz * Oc);

        // ---- wait for the row above to publish column w ----
        if (r > 0 && tid == 0) {
            while (ld_acq(&g_progress[bid - 1]) <= (unsigned)w) __nanosleep(32);
        }
        __syncthreads();   // S1

        // ---- prefetch c_top for this thread's epilogue outputs (hidden under MMA) ----
        float ctop_r[2][4];
#pragma unroll
        for (int p = 0; p < 2; ++p)
#pragma unroll
            for (int nt = 0; nt < 4; ++nt) {
                if (r > 0)
                    ctop_r[p][nt] = g_cbuf[topoff + (size_t)(bbB + p * 16) * Oc + (chB + nt * 2)];
                else
                    ctop_r[p][nt] = 0.f;
            }

        // ---- stage h_top (A rows 0..31) and x (A cols 128..143, both halves) ----
        if (r > 0) {
            const uint4* src = reinterpret_cast<const uint4*>(g_hbuf + topoff);
            int b = tid >> 4, s = tid & 15;          // 32 rows x 16 uint4 = 512
            *reinterpret_cast<uint4*>(sA + b * ASTR + s * 8) = src[tid];
        }
        {
            int b = tid >> 4, ci = tid & 15;         // 32 x 16 = 512
            __half hx = __float2half(x[(size_t)tid * (Hh * Ww) + ph * Ww + pw]);
            sA[b * ASTR + 128 + ci]        = hx;
            sA[(32 + b) * ASTR + 128 + ci] = hx;
        }
        __syncthreads();   // S2: A ready

        // ---- MMA: C(64x512) += A(64x144) * B(144x512); per warp 32 n-cols ----
        float acc[4][4][4];
#pragma unroll
        for (int mt = 0; mt < 4; ++mt)
#pragma unroll
            for (int nt = 0; nt < 4; ++nt)
#pragma unroll
                for (int q = 0; q < 4; ++q) acc[mt][nt][q] = 0.f;

#pragma unroll
        for (int k = 0; k < 9; ++k) {
            unsigned af[4][4];
#pragma unroll
            for (int mt = 0; mt < 4; ++mt) {
                const __half* ap = Abase + mt * 16 * ASTR + k * 16;
                af[mt][0] = lds_u32(ap);
                af[mt][1] = lds_u32(ap + 8 * ASTR);
                af[mt][2] = lds_u32(ap + 8);
                af[mt][3] = lds_u32(ap + 8 * ASTR + 8);
            }
#pragma unroll
            for (int nt = 0; nt < 4; ++nt) {
                const __half* bp = Bbase + nt * 8 * BSTR + k * 16;
                unsigned b0 = lds_u32(bp);
                unsigned b1 = lds_u32(bp + 8);
#pragma unroll
                for (int mt = 0; mt < 4; ++mt)
                    mma16816(acc[mt][nt], af[mt], b0, b1);
            }
        }
        __syncthreads();   // S3: all warps done reading sA before epilogue rewrites h_left

        // ---- epilogue: gates, cell update, publish h/c ----
#pragma unroll
        for (int p = 0; p < 2; ++p) {
#pragma unroll
            for (int nt = 0; nt < 4; ++nt) {
                float* c0 = acc[p][nt];       // branch0 (top):  rows p*16..
                float* c1 = acc[p + 2][nt];   // branch1 (left): rows 32+p*16..
                float rA0 = __shfl_xor_sync(0xffffffffu, oddt ? c0[0] : c0[2], 1);
                float rB0 = __shfl_xor_sync(0xffffffffu, oddt ? c0[1] : c0[3], 1);
                float rA1 = __shfl_xor_sync(0xffffffffu, oddt ? c1[0] : c1[2], 1);
                float rB1 = __shfl_xor_sync(0xffffffffu, oddt ? c1[1] : c1[3], 1);
                float pi0, pf0, pg0, po0, pi1, pf1, pg1, po1;
                if (!oddt) { pi0 = c0[0]; pf0 = c0[1]; pg0 = rA0;  po0 = rB0;
                             pi1 = c1[0]; pf1 = c1[1]; pg1 = rA1;  po1 = rB1; }
                else       { pi0 = rA0;  pf0 = rB0;  pg0 = c0[2]; po0 = c0[3];
                             pi1 = rA1;  pf1 = rB1;  pg1 = c1[2]; po1 = c1[3]; }

                const int bb = bbB + p * 16;
                const int ch = chB + nt * 2;

                const float bi = sBias[ch],        bf2 = sBias[128 + ch];
                const float bg = sBias[256 + ch],  bo  = sBias[384 + ch];
                const float bv = sBias[512 + ch];

                const float ctop = ctop_r[p][nt];
                const float clft = sCl[bb * Oc + ch];

                const float i0 = sigf(pi0 + bi), f0 = sigf(pf0 + bf2);
                const float g0 = tnhf(pg0 + bg), o0 = sigf(po0 + bo);
                const float cn0 = f0 * ctop + i0 * g0;
                const float h0  = o0 * tnhf(cn0);

                const float i1 = sigf(pi1 + bi), f1 = sigf(pf1 + bf2);
                const float g1 = tnhf(pg1 + bg), o1 = sigf(po1 + bo);
                const float cn1 = f1 * clft + i1 * g1;
                const float h1  = o1 * tnhf(cn1);

                const float ct = ws0 * cn0 + ws1 * cn1 + bv;
                const float ht = ws0 * h0  + ws1 * h1  + bv;

                sCl[bb * Oc + ch] = ct;
                g_cbuf[rowoff + bb * Oc + ch] = ct;
                const __half hh = __float2half(ht);
                sA[(32 + bb) * ASTR + ch] = hh;        // h_left for next column
                g_hbuf[rowoff + bb * Oc + ch] = hh;    // h_top for row below + output
            }
        }
        __syncthreads();   // S4: all writes done before publish
        if (tid == 0) st_rel(&g_progress[bid], (unsigned)(w + 1));
    }

    // ---- output epilogue: transpose f16 row history -> coalesced fp32 stores ----
    // out[d][ch][b][ph][pw] = h[r][w][b][ch], w = fx ? 127-pw : pw
    __half* tile = reinterpret_cast<__half*>(smem);   // reuse sB region (~35 KB)
    float* outp = out + (size_t)d * Oc * Bsz * Hh * Ww;
    __syncthreads();
#pragma unroll 1
    for (int b = 0; b < Bsz; ++b) {
#pragma unroll 1
        for (int idx = tid; idx < 128 * 64; idx += THREADS) {   // u32 units: 128 w x 64
            int wq = idx >> 6, s = idx & 63;
            unsigned v = *reinterpret_cast<const unsigned*>(
                g_hbuf + ((size_t)bid * Ww + wq) * (Bsz * Oc) + b * Oc + s * 2);
            *reinterpret_cast<unsigned*>(tile + wq * TTS + s * 2) = v;
        }
        __syncthreads();
#pragma unroll 1
        for (int idx = tid; idx < 128 * 128; idx += THREADS) {
            int ch = idx >> 7, pw = idx & 127;
            int ww = fx ? (127 - pw) : pw;
            outp[(((size_t)ch * Bsz + b) * Hh + ph) * Ww + pw] =
                __half2float(tile[ww * TTS + ch]);
        }
        __syncthreads();
    }
}

// ---------------- launch ----------------
extern "C" void kernel_launch(void* const* d_in, const int* in_sizes, int n_in,
                              void* d_out, int out_size)
{
    const float* x     = (const float*)d_in[0];
    const float* w_ii  = (const float*)d_in[1];
    const float* w_hi  = (const float*)d_in[2];
    const float* b_i   = (const float*)d_in[3];
    const float* w_if  = (const float*)d_in[4];
    const float* w_hf  = (const float*)d_in[5];
    const float* b_f   = (const float*)d_in[6];
    const float* w_ig  = (const float*)d_in[7];
    const float* w_hg  = (const float*)d_in[8];
    const float* b_g   = (const float*)d_in[9];
    const float* w_io  = (const float*)d_in[10];
    const float* w_ho  = (const float*)d_in[11];
    const float* b_o   = (const float*)d_in[12];
    const float* wsum  = (const float*)d_in[13];
    const float* biasv = (const float*)d_in[14];
    float* out = (float*)d_out;

    cudaFuncSetAttribute(mdlstm_kernel,
                         cudaFuncAttributeMaxDynamicSharedMemorySize, SMEM_TOTAL);

    init_progress_kernel<<<1, 128>>>();
    mdlstm_kernel<<<128, THREADS, SMEM_TOTAL>>>(
        x, w_ii, w_hi, b_i, w_if, w_hf, b_f, w_ig, w_hg, b_g,
        w_io, w_ho, b_o, wsum, biasv, out);
}

// round 6
// speedup vs baseline: 1.2698x; 1.0946x over previous
#include <cuda_runtime.h>
#include <cuda_fp16.h>
#include <cstddef>
#include <cstdint>

// ---------------- problem constants ----------------
#define Bsz   32
#define CINc  16
#define Hh    32
#define Ww    128
#define Oc    128
#define NTOT  512          // 128 channels x 4 gates, interleaved n = ch*4 + gate
#define ASTR  168          // padded half-stride
#define BSTR  168
#define THREADS 512

// ---------------- shared memory layout (bytes) ----------------
// A region rows: 0-31 = top (h_top | x), 32-63 = left buf0, 64-95 = left buf1
#define OFF_B     0
#define SZ_B      (NTOT * BSTR * 2)            // 172032
#define OFF_A     (OFF_B + SZ_B)               // 172032
#define SZ_A      (96 * ASTR * 2)              // 32256
#define OFF_BIAS  (OFF_A + SZ_A)               // 204288
#define SZ_BIAS   (5 * Oc * 4)                 // 2560
#define SMEM_TOTAL (OFF_BIAS + SZ_BIAS)        // 206848

// transpose tile stride (halves); 69 words odd -> conflict-free strided reads
#define TTS 138

// ---------------- global scratch ----------------
// [bid][w][b][ch] with bid = d*32 + r  (direction-frame row)
__device__ __align__(256) __half  g_hbuf[(size_t)128 * 128 * 32 * 128];
__device__ __align__(256) float   g_cbuf[(size_t)128 * 128 * 32 * 128];
__device__ unsigned               g_progress[128];

// ---------------- helpers ----------------
__device__ __forceinline__ float tnhf(float x) {
    float y;
    asm("tanh.approx.f32 %0, %1;" : "=f"(y) : "f"(x));
    return y;
}
__device__ __forceinline__ float sigf(float x) {
    return fmaf(tnhf(0.5f * x), 0.5f, 0.5f);
}
__device__ __forceinline__ unsigned ld_acq(const unsigned* p) {
    unsigned v;
    asm volatile("ld.acquire.gpu.global.b32 %0, [%1];" : "=r"(v) : "l"(p));
    return v;
}
__device__ __forceinline__ void st_rel(unsigned* p, unsigned v) {
    asm volatile("st.release.gpu.global.b32 [%0], %1;" :: "l"(p), "r"(v) : "memory");
}
__device__ __forceinline__ void mma16816(float* c, const unsigned* a, unsigned b0, unsigned b1) {
    asm volatile(
        "mma.sync.aligned.m16n8k16.row.col.f32.f16.f16.f32 "
        "{%0,%1,%2,%3}, {%4,%5,%6,%7}, {%8,%9}, {%0,%1,%2,%3};"
        : "+f"(c[0]), "+f"(c[1]), "+f"(c[2]), "+f"(c[3])
        : "r"(a[0]), "r"(a[1]), "r"(a[2]), "r"(a[3]), "r"(b0), "r"(b1));
}
__device__ __forceinline__ unsigned lds_u32(const __half* p) {
    return *reinterpret_cast<const unsigned*>(p);
}

__global__ void init_progress_kernel() {
    if (threadIdx.x < 128) g_progress[threadIdx.x] = 0u;
}

// ---------------- main persistent kernel: one CTA per (direction, row) ----------------
__global__ void __launch_bounds__(THREADS, 1) mdlstm_kernel(
    const float* __restrict__ x,
    const float* __restrict__ w_ii, const float* __restrict__ w_hi, const float* __restrict__ b_i,
    const float* __restrict__ w_if, const float* __restrict__ w_hf, const float* __restrict__ b_f,
    const float* __restrict__ w_ig, const float* __restrict__ w_hg, const float* __restrict__ b_g,
    const float* __restrict__ w_io, const float* __restrict__ w_ho, const float* __restrict__ b_o,
    const float* __restrict__ wsum, const float* __restrict__ biasv,
    float* __restrict__ out)
{
    extern __shared__ char smem[];
    __half* sB    = reinterpret_cast<__half*>(smem + OFF_B);
    __half* sA    = reinterpret_cast<__half*>(smem + OFF_A);
    float*  sBias = reinterpret_cast<float*>(smem + OFF_BIAS);

    const int tid  = threadIdx.x;
    const int lane = tid & 31;
    const int wid  = tid >> 5;          // 0..15
    const int bid  = blockIdx.x;
    const int d    = bid >> 5;
    const int r    = bid & 31;
    const bool fx  = (d & 1) != 0;
    const bool fy  = (d & 2) != 0;
    const int  ph  = fy ? (Hh - 1 - r) : r;

    // ---- stage weights: sB[n][k], n = ch*4 + gate, k = 0..127 (Wh) | 128..143 (Wi) ----
    {
        const float* whArr[4] = {w_hi, w_hf, w_hg, w_ho};
        const float* wiArr[4] = {w_ii, w_if, w_ig, w_io};
        for (int gate = 0; gate < 4; ++gate) {
            const float* wh = whArr[gate] + (size_t)d * Oc * Oc;
            for (int idx = tid; idx < Oc * Oc; idx += THREADS) {
                int ch = idx >> 7, k = idx & 127;
                sB[(ch * 4 + gate) * BSTR + k] = __float2half(wh[idx]);
            }
            const float* wi = wiArr[gate] + (size_t)d * Oc * CINc;
            for (int idx = tid; idx < Oc * CINc; idx += THREADS) {
                int ch = idx >> 4, k = idx & 15;
                sB[(ch * 4 + gate) * BSTR + 128 + k] = __float2half(wi[idx]);
            }
        }
        const float* bArr[4] = {b_i, b_f, b_g, b_o};
        sBias[tid] = bArr[tid >> 7][(size_t)d * Oc + (tid & 127)];
        if (tid < 128) sBias[512 + tid] = biasv[(size_t)d * Oc + tid];
        // zero h columns of left buf0 (read at w=0); buf1 fully written by epilogue(w=0)
        for (int idx = tid; idx < 32 * 128; idx += THREADS) {
            int b = idx >> 7, c = idx & 127;
            sA[(32 + b) * ASTR + c] = __float2half(0.f);
        }
        if (r == 0) {   // h_top = 0 forever for the first row
            for (int idx = tid; idx < 32 * 128; idx += THREADS) {
                int b = idx >> 7, c = idx & 127;
                sA[b * ASTR + c] = __float2half(0.f);
            }
        }
    }
    const float ws0 = wsum[d * 2 + 0];
    const float ws1 = wsum[d * 2 + 1];
    __syncthreads();

    const int g = lane >> 2, t = lane & 3;
    const bool oddt = (t & 1) != 0;
    const __half* AbaseT = sA + g * ASTR + t * 2;                  // mt 0,1 (top)
    const __half* Bbase  = sB + ((wid << 5) + g) * BSTR + t * 2;   // 32 n-cols per warp

    // per-thread epilogue ownership
    const int chB = (wid << 3) + (t >> 1);          // + nt*2
    const int bbB = g + (oddt ? 8 : 0);             // + p*16
    const int sx_b = tid >> 4, sx_ci = tid & 15;    // x staging mapping

    float cleft[2][4];                               // c_left lives in registers
#pragma unroll
    for (int p = 0; p < 2; ++p)
#pragma unroll
        for (int nt = 0; nt < 4; ++nt) cleft[p][nt] = 0.f;

    unsigned avail = 0;                              // cached producer progress
    float xreg = x[(size_t)tid * (Hh * Ww) + ph * Ww + (fx ? (Ww - 1) : 0)];

#pragma unroll 1
    for (int w = 0; w < Ww; ++w) {
        const int cur = w & 1, nxt = cur ^ 1;
        const size_t rowoff = ((size_t)bid * Ww + w) * (Bsz * Oc);
        const size_t topoff = rowoff - (size_t)Ww * (Bsz * Oc);

        // ---- store x(w) into top rows + current left buffer (safe: prior S4 passed) ----
        {
            __half hx = __float2half(xreg);
            sA[sx_b * ASTR + 128 + sx_ci] = hx;
            sA[(32 + (cur << 5) + sx_b) * ASTR + 128 + sx_ci] = hx;
        }
        // ---- prefetch x(w+1) (hidden under this whole step) ----
        if (w + 1 < Ww) {
            int pwn = fx ? (Ww - 2 - w) : (w + 1);
            xreg = x[(size_t)tid * (Hh * Ww) + ph * Ww + pwn];
        }

        // ---- wait for the row above to publish column w (cached progress) ----
        if (r > 0 && tid == 0 && avail <= (unsigned)w) {
            avail = ld_acq(&g_progress[bid - 1]);
            while (avail <= (unsigned)w) { __nanosleep(32); avail = ld_acq(&g_progress[bid - 1]); }
        }
        __syncthreads();   // S1

        // ---- prefetch c_top for this thread's outputs (hidden under MMA) ----
        float ctop_r[2][4];
#pragma unroll
        for (int p = 0; p < 2; ++p)
#pragma unroll
            for (int nt = 0; nt < 4; ++nt) {
                if (r > 0)
                    ctop_r[p][nt] = g_cbuf[topoff + (size_t)(bbB + p * 16) * Oc + (chB + nt * 2)];
                else
                    ctop_r[p][nt] = 0.f;
            }

        // ---- stage h_top (A rows 0..31) ----
        if (r > 0) {
            const uint4* src = reinterpret_cast<const uint4*>(g_hbuf + topoff);
            int b = tid >> 4, s = tid & 15;          // 32 rows x 16 uint4 = 512
            *reinterpret_cast<uint4*>(sA + b * ASTR + s * 8) = src[tid];
        }
        __syncthreads();   // S2: A ready

        const __half* AbaseL = sA + (32 + (cur << 5) + g) * ASTR + t * 2;   // mt 2,3 (left)

        // ---- two n-passes: MMA(64x256) + immediate epilogue; acc stays small ----
#pragma unroll
        for (int pass = 0; pass < 2; ++pass) {
            float acc[4][2][4];
#pragma unroll
            for (int mt = 0; mt < 4; ++mt)
#pragma unroll
                for (int ntl = 0; ntl < 2; ++ntl)
#pragma unroll
                    for (int q = 0; q < 4; ++q) acc[mt][ntl][q] = 0.f;

#pragma unroll
            for (int k = 0; k < 9; ++k) {
                unsigned af[4][4];
#pragma unroll
                for (int mt = 0; mt < 2; ++mt) {
                    const __half* ap = AbaseT + mt * 16 * ASTR + k * 16;
                    af[mt][0] = lds_u32(ap);
                    af[mt][1] = lds_u32(ap + 8 * ASTR);
                    af[mt][2] = lds_u32(ap + 8);
                    af[mt][3] = lds_u32(ap + 8 * ASTR + 8);
                }
#pragma unroll
                for (int mt = 0; mt < 2; ++mt) {
                    const __half* ap = AbaseL + mt * 16 * ASTR + k * 16;
                    af[2 + mt][0] = lds_u32(ap);
                    af[2 + mt][1] = lds_u32(ap + 8 * ASTR);
                    af[2 + mt][2] = lds_u32(ap + 8);
                    af[2 + mt][3] = lds_u32(ap + 8 * ASTR + 8);
                }
#pragma unroll
                for (int ntl = 0; ntl < 2; ++ntl) {
                    const __half* bp = Bbase + (pass * 2 + ntl) * 8 * BSTR + k * 16;
                    unsigned b0 = lds_u32(bp);
                    unsigned b1 = lds_u32(bp + 8);
#pragma unroll
                    for (int mt = 0; mt < 4; ++mt)
                        mma16816(acc[mt][ntl], af[mt], b0, b1);
                }
            }

            // ---- epilogue for this pass (no barrier: disjoint per-thread data,
            //      h_left written into the OTHER buffer) ----
#pragma unroll
            for (int p = 0; p < 2; ++p) {
#pragma unroll
                for (int ntl = 0; ntl < 2; ++ntl) {
                    const int nt = pass * 2 + ntl;
                    float* c0 = acc[p][ntl];       // top branch rows
                    float* c1 = acc[p + 2][ntl];   // left branch rows
                    float rA0 = __shfl_xor_sync(0xffffffffu, oddt ? c0[0] : c0[2], 1);
                    float rB0 = __shfl_xor_sync(0xffffffffu, oddt ? c0[1] : c0[3], 1);
                    float rA1 = __shfl_xor_sync(0xffffffffu, oddt ? c1[0] : c1[2], 1);
                    float rB1 = __shfl_xor_sync(0xffffffffu, oddt ? c1[1] : c1[3], 1);
                    float pi0, pf0, pg0, po0, pi1, pf1, pg1, po1;
                    if (!oddt) { pi0 = c0[0]; pf0 = c0[1]; pg0 = rA0;  po0 = rB0;
                                 pi1 = c1[0]; pf1 = c1[1]; pg1 = rA1;  po1 = rB1; }
                    else       { pi0 = rA0;  pf0 = rB0;  pg0 = c0[2]; po0 = c0[3];
                                 pi1 = rA1;  pf1 = rB1;  pg1 = c1[2]; po1 = c1[3]; }

                    const int bb = bbB + p * 16;
                    const int ch = chB + nt * 2;

                    const float bi = sBias[ch],        bf2 = sBias[128 + ch];
                    const float bg = sBias[256 + ch],  bo  = sBias[384 + ch];
                    const float bv = sBias[512 + ch];

                    const float ctop = ctop_r[p][nt];
                    const float clft = cleft[p][nt];

                    const float i0 = sigf(pi0 + bi), f0 = sigf(pf0 + bf2);
                    const float g0 = tnhf(pg0 + bg), o0 = sigf(po0 + bo);
                    const float cn0 = f0 * ctop + i0 * g0;
                    const float h0  = o0 * tnhf(cn0);

                    const float i1 = sigf(pi1 + bi), f1 = sigf(pf1 + bf2);
                    const float g1 = tnhf(pg1 + bg), o1 = sigf(po1 + bo);
                    const float cn1 = f1 * clft + i1 * g1;
                    const float h1  = o1 * tnhf(cn1);

                    const float ct = ws0 * cn0 + ws1 * cn1 + bv;
                    const float ht = ws0 * h0  + ws1 * h1  + bv;

                    cleft[p][nt] = ct;
                    g_cbuf[rowoff + bb * Oc + ch] = ct;
                    const __half hh = __float2half(ht);
                    sA[(32 + (nxt << 5) + bb) * ASTR + ch] = hh;   // h_left, other buffer
                    g_hbuf[rowoff + bb * Oc + ch] = hh;            // for row below + output
                }
            }
        }

        __syncthreads();   // S4: all writes done before publish
        if (tid == 0) st_rel(&g_progress[bid], (unsigned)(w + 1));
    }

    // ---- output epilogue: transpose f16 row history -> coalesced fp32 stores ----
    // out[d][ch][b][ph][pw] = h[r][w][b][ch], w = fx ? 127-pw : pw
    __half* tile = reinterpret_cast<__half*>(smem);   // reuse sB region (~35 KB)
    float* outp = out + (size_t)d * Oc * Bsz * Hh * Ww;
    __syncthreads();
#pragma unroll 1
    for (int b = 0; b < Bsz; ++b) {
#pragma unroll 1
        for (int idx = tid; idx < 128 * 64; idx += THREADS) {   // u32 units: 128 w x 64
            int wq = idx >> 6, s = idx & 63;
            unsigned v = *reinterpret_cast<const unsigned*>(
                g_hbuf + ((size_t)bid * Ww + wq) * (Bsz * Oc) + b * Oc + s * 2);
            *reinterpret_cast<unsigned*>(tile + wq * TTS + s * 2) = v;
        }
        __syncthreads();
#pragma unroll 1
        for (int idx = tid; idx < 128 * 128; idx += THREADS) {
            int ch = idx >> 7, pw = idx & 127;
            int ww = fx ? (127 - pw) : pw;
            outp[(((size_t)ch * Bsz + b) * Hh + ph) * Ww + pw] =
                __half2float(tile[ww * TTS + ch]);
        }
        __syncthreads();
    }
}

// ---------------- launch ----------------
extern "C" void kernel_launch(void* const* d_in, const int* in_sizes, int n_in,
                              void* d_out, int out_size)
{
    const float* x     = (const float*)d_in[0];
    const float* w_ii  = (const float*)d_in[1];
    const float* w_hi  = (const float*)d_in[2];
    const float* b_i   = (const float*)d_in[3];
    const float* w_if  = (const float*)d_in[4];
    const float* w_hf  = (const float*)d_in[5];
    const float* b_f   = (const float*)d_in[6];
    const float* w_ig  = (const float*)d_in[7];
    const float* w_hg  = (const float*)d_in[8];
    const float* b_g   = (const float*)d_in[9];
    const float* w_io  = (const float*)d_in[10];
    const float* w_ho  = (const float*)d_in[11];
    const float* b_o   = (const float*)d_in[12];
    const float* wsum  = (const float*)d_in[13];
    const float* biasv = (const float*)d_in[14];
    float* out = (float*)d_out;

    cudaFuncSetAttribute(mdlstm_kernel,
                         cudaFuncAttributeMaxDynamicSharedMemorySize, SMEM_TOTAL);

    init_progress_kernel<<<1, 128>>>();
    mdlstm_kernel<<<128, THREADS, SMEM_TOTAL>>>(
        x, w_ii, w_hi, b_i, w_if, w_hf, b_f, w_ig, w_hg, b_g,
        w_io, w_ho, b_o, wsum, biasv, out);
}

// round 7
// speedup vs baseline: 1.9547x; 1.5394x over previous
#include <cuda_runtime.h>
#include <cuda_fp16.h>
#include <cstddef>
#include <cstdint>

// ---------------- problem constants ----------------
#define Bsz   32
#define CINc  16
#define Hh    32
#define Ww    128
#define Oc    128
#define NTOT  512          // 128 channels x 4 gates, interleaved n = ch*4 + gate
#define ASTR  168          // padded half-stride (168 = conflict-free for LDSM rows)
#define BSTR  168
#define THREADS 512

// ---------------- shared memory layout (bytes) ----------------
// A region rows: 0-31 = top (h_top | x), 32-63 = left buf0, 64-95 = left buf1
#define OFF_B     0
#define SZ_B      (NTOT * BSTR * 2)            // 172032
#define OFF_A     (OFF_B + SZ_B)               // 172032
#define SZ_A      (96 * ASTR * 2)              // 32256
#define OFF_BIAS  (OFF_A + SZ_A)               // 204288
#define SZ_BIAS   (5 * Oc * 4)                 // 2560
#define SMEM_TOTAL (OFF_BIAS + SZ_BIAS)        // 206848

// transpose tile stride (halves); 69 words odd -> conflict-free strided reads
#define TTS 138

// ---------------- global scratch ----------------
// g_hbuf: canonical [bid][w][b][ch]   (A-operand staging + output reconstruction)
// g_cbuf: thread-packed [bid][w][p*2048 + tid*4 + nt]  (c handoff, tid-symmetric)
__device__ __align__(256) __half  g_hbuf[(size_t)128 * 128 * 32 * 128];
__device__ __align__(256) float   g_cbuf[(size_t)128 * 128 * 32 * 128];
__device__ unsigned               g_progress[128];

// ---------------- helpers ----------------
__device__ __forceinline__ float tnhf(float x) {
    float y;
    asm("tanh.approx.f32 %0, %1;" : "=f"(y) : "f"(x));
    return y;
}
__device__ __forceinline__ float sigf(float x) {
    return fmaf(tnhf(0.5f * x), 0.5f, 0.5f);
}
__device__ __forceinline__ unsigned ld_acq(const unsigned* p) {
    unsigned v;
    asm volatile("ld.acquire.gpu.global.b32 %0, [%1];" : "=r"(v) : "l"(p));
    return v;
}
__device__ __forceinline__ void st_rel(unsigned* p, unsigned v) {
    asm volatile("st.release.gpu.global.b32 [%0], %1;" :: "l"(p), "r"(v) : "memory");
}
__device__ __forceinline__ void mma16816(float* c, const unsigned* a, unsigned b0, unsigned b1) {
    asm volatile(
        "mma.sync.aligned.m16n8k16.row.col.f32.f16.f16.f32 "
        "{%0,%1,%2,%3}, {%4,%5,%6,%7}, {%8,%9}, {%0,%1,%2,%3};"
        : "+f"(c[0]), "+f"(c[1]), "+f"(c[2]), "+f"(c[3])
        : "r"(a[0]), "r"(a[1]), "r"(a[2]), "r"(a[3]), "r"(b0), "r"(b1));
}
__device__ __forceinline__ void ldsm_x4(unsigned* r, unsigned addr) {
    asm volatile(
        "ldmatrix.sync.aligned.m8n8.x4.shared.b16 {%0,%1,%2,%3}, [%4];"
        : "=r"(r[0]), "=r"(r[1]), "=r"(r[2]), "=r"(r[3]) : "r"(addr));
}

__global__ void init_progress_kernel() {
    if (threadIdx.x < 128) g_progress[threadIdx.x] = 0u;
}

// ---------------- main persistent kernel: one CTA per (direction, row) ----------------
__global__ void __launch_bounds__(THREADS, 1) mdlstm_kernel(
    const float* __restrict__ x,
    const float* __restrict__ w_ii, const float* __restrict__ w_hi, const float* __restrict__ b_i,
    const float* __restrict__ w_if, const float* __restrict__ w_hf, const float* __restrict__ b_f,
    const float* __restrict__ w_ig, const float* __restrict__ w_hg, const float* __restrict__ b_g,
    const float* __restrict__ w_io, const float* __restrict__ w_ho, const float* __restrict__ b_o,
    const float* __restrict__ wsum, const float* __restrict__ biasv,
    float* __restrict__ out)
{
    extern __shared__ char smem[];
    __half* sB    = reinterpret_cast<__half*>(smem + OFF_B);
    __half* sA    = reinterpret_cast<__half*>(smem + OFF_A);
    float*  sBias = reinterpret_cast<float*>(smem + OFF_BIAS);

    const int tid  = threadIdx.x;
    const int lane = tid & 31;
    const int wid  = tid >> 5;          // 0..15
    const int bid  = blockIdx.x;
    const int d    = bid >> 5;
    const int r    = bid & 31;
    const bool fx  = (d & 1) != 0;
    const bool fy  = (d & 2) != 0;
    const int  ph  = fy ? (Hh - 1 - r) : r;

    // ---- stage weights: sB[n][k], n = ch*4 + gate, k = 0..127 (Wh) | 128..143 (Wi) ----
    {
        const float* whArr[4] = {w_hi, w_hf, w_hg, w_ho};
        const float* wiArr[4] = {w_ii, w_if, w_ig, w_io};
        for (int gate = 0; gate < 4; ++gate) {
            const float* wh = whArr[gate] + (size_t)d * Oc * Oc;
            for (int idx = tid; idx < Oc * Oc; idx += THREADS) {
                int ch = idx >> 7, k = idx & 127;
                sB[(ch * 4 + gate) * BSTR + k] = __float2half(wh[idx]);
            }
            const float* wi = wiArr[gate] + (size_t)d * Oc * CINc;
            for (int idx = tid; idx < Oc * CINc; idx += THREADS) {
                int ch = idx >> 4, k = idx & 15;
                sB[(ch * 4 + gate) * BSTR + 128 + k] = __float2half(wi[idx]);
            }
        }
        const float* bArr[4] = {b_i, b_f, b_g, b_o};
        sBias[tid] = bArr[tid >> 7][(size_t)d * Oc + (tid & 127)];
        if (tid < 128) sBias[512 + tid] = biasv[(size_t)d * Oc + tid];
        // zero h columns of left buf0 (read at w=0); buf1 fully written by epilogue(w=0)
        for (int idx = tid; idx < 32 * 128; idx += THREADS) {
            int b = idx >> 7, c = idx & 127;
            sA[(32 + b) * ASTR + c] = __float2half(0.f);
        }
        if (r == 0) {   // h_top = 0 forever for the first row
            for (int idx = tid; idx < 32 * 128; idx += THREADS) {
                int b = idx >> 7, c = idx & 127;
                sA[b * ASTR + c] = __float2half(0.f);
            }
        }
    }
    const float ws0 = wsum[d * 2 + 0];
    const float ws1 = wsum[d * 2 + 1];
    __syncthreads();

    const int g = lane >> 2, t = lane & 3;
    const bool oddt = (t & 1) != 0;

    // per-thread epilogue ownership
    const int chB = (wid << 3) + (t >> 1);          // + nt*2
    const int bbB = g + (oddt ? 8 : 0);             // + p*16
    const int sx_b = tid >> 4, sx_ci = tid & 15;    // x / h_top staging mapping
    const int n0 = wid << 5;                        // warp's 32 n-cols

    // ldmatrix per-lane address roles
    const unsigned sAu = (unsigned)__cvta_generic_to_shared(sA);
    const unsigned sBu = (unsigned)__cvta_generic_to_shared(sB);
    const int aro  = (lane & 7) + ((lane >> 3) & 1) * 8;   // row within 16
    const int ako  = (lane >> 4) * 8;                      // k-half offset
    const unsigned aAtopU   = sAu + (unsigned)((aro * ASTR + ako) * 2);
    const unsigned aAleftU0 = sAu + (unsigned)(((32 + aro) * ASTR + ako) * 2);
    const unsigned aBU      = sBu + (unsigned)(((n0 + ((lane >> 4) & 1) * 8 + (lane & 7)) * BSTR
                                                + ((lane >> 3) & 1) * 8) * 2);

    float cleft[2][4];                               // c_left lives in registers
#pragma unroll
    for (int p = 0; p < 2; ++p)
#pragma unroll
        for (int nt = 0; nt < 4; ++nt) cleft[p][nt] = 0.f;

    unsigned avail = 0;                              // cached producer progress
    const float* xrow = x + (size_t)tid * (Hh * Ww) + (size_t)ph * Ww;
    const int xm = fx ? 3 : 0;                       // quad-index flip mask
    float4 xq = make_float4(0.f, 0.f, 0.f, 0.f);

#pragma unroll 1
    for (int w = 0; w < Ww; ++w) {
        const int cur = w & 1, nxt = cur ^ 1;
        const size_t rowoff = ((size_t)bid * Ww + w) * (Bsz * Oc);
        const size_t topoff = rowoff - (size_t)Ww * (Bsz * Oc);

        // ---- x: load a float4 every 4th step, select element branchlessly ----
        if ((w & 3) == 0)
            xq = *reinterpret_cast<const float4*>(xrow + (fx ? (124 - w) : w));
        {
            const int e = (w & 3) ^ xm;
            float s01 = (e & 1) ? xq.y : xq.x;
            float s23 = (e & 1) ? xq.w : xq.z;
            float xv  = (e & 2) ? s23 : s01;
            __half hx = __float2half(xv);
            sA[sx_b * ASTR + 128 + sx_ci] = hx;                      // top rows
            sA[(32 + (cur << 5) + sx_b) * ASTR + 128 + sx_ci] = hx;  // current left buf
        }

        // ---- wait for the row above to publish column w (cached progress) ----
        if (r > 0 && tid == 0 && avail <= (unsigned)w) {
            avail = ld_acq(&g_progress[bid - 1]);
            while (avail <= (unsigned)w) { __nanosleep(32); avail = ld_acq(&g_progress[bid - 1]); }
        }
        __syncthreads();   // S1

        // ---- c_top: coalesced thread-packed load (hidden under pass-0 MMA) ----
        float cc[2][4];    // holds ctop, then cn0 in place
        if (r > 0) {
            float4 q0 = *reinterpret_cast<const float4*>(g_cbuf + topoff + (tid << 2));
            float4 q1 = *reinterpret_cast<const float4*>(g_cbuf + topoff + 2048 + (tid << 2));
            cc[0][0] = q0.x; cc[0][1] = q0.y; cc[0][2] = q0.z; cc[0][3] = q0.w;
            cc[1][0] = q1.x; cc[1][1] = q1.y; cc[1][2] = q1.z; cc[1][3] = q1.w;
        } else {
#pragma unroll
            for (int p = 0; p < 2; ++p)
#pragma unroll
                for (int nt = 0; nt < 4; ++nt) cc[p][nt] = 0.f;
        }

        // ---- stage h_top (A rows 0..31), coalesced uint4 ----
        if (r > 0) {
            const uint4* src = reinterpret_cast<const uint4*>(g_hbuf + topoff);
            *reinterpret_cast<uint4*>(sA + sx_b * ASTR + sx_ci * 8) = src[tid];
        }
        __syncthreads();   // S2: A ready

        // ================= pass 0: TOP branch (A rows 0-31) =================
        float h0s[2][4];
        {
            float acc[2][4][4];
#pragma unroll
            for (int mt = 0; mt < 2; ++mt)
#pragma unroll
                for (int nt = 0; nt < 4; ++nt)
#pragma unroll
                    for (int q = 0; q < 4; ++q) acc[mt][nt][q] = 0.f;

#pragma unroll
            for (int k = 0; k < 9; ++k) {
                unsigned a0[4], a1[4], bp0[4], bp1[4];
                ldsm_x4(a0, aAtopU + (unsigned)(k * 32));
                ldsm_x4(a1, aAtopU + (unsigned)(16 * ASTR * 2 + k * 32));
                ldsm_x4(bp0, aBU + (unsigned)(k * 32));
                ldsm_x4(bp1, aBU + (unsigned)(16 * BSTR * 2 + k * 32));
                mma16816(acc[0][0], a0, bp0[0], bp0[1]);
                mma16816(acc[0][1], a0, bp0[2], bp0[3]);
                mma16816(acc[0][2], a0, bp1[0], bp1[1]);
                mma16816(acc[0][3], a0, bp1[2], bp1[3]);
                mma16816(acc[1][0], a1, bp0[0], bp0[1]);
                mma16816(acc[1][1], a1, bp0[2], bp0[3]);
                mma16816(acc[1][2], a1, bp1[0], bp1[1]);
                mma16816(acc[1][3], a1, bp1[2], bp1[3]);
            }

            // top-branch epilogue: cn0 (into cc), h0
#pragma unroll
            for (int p = 0; p < 2; ++p) {
#pragma unroll
                for (int nt = 0; nt < 4; ++nt) {
                    float* c0 = acc[p][nt];
                    float rA = __shfl_xor_sync(0xffffffffu, oddt ? c0[0] : c0[2], 1);
                    float rB = __shfl_xor_sync(0xffffffffu, oddt ? c0[1] : c0[3], 1);
                    float pi, pf, pg, po;
                    if (!oddt) { pi = c0[0]; pf = c0[1]; pg = rA;    po = rB; }
                    else       { pi = rA;    pf = rB;    pg = c0[2]; po = c0[3]; }
                    const int ch = chB + nt * 2;
                    const float i0 = sigf(pi + sBias[ch]);
                    const float f0 = sigf(pf + sBias[128 + ch]);
                    const float g0 = tnhf(pg + sBias[256 + ch]);
                    const float o0 = sigf(po + sBias[384 + ch]);
                    const float cn0 = f0 * cc[p][nt] + i0 * g0;
                    cc[p][nt] = cn0;
                    h0s[p][nt] = o0 * tnhf(cn0);
                }
            }
        }

        // ================= pass 1: LEFT branch (A rows 32+cur*32..) =================
        {
            const unsigned aAleftU = aAleftU0 + (unsigned)(cur * (32 * ASTR * 2));
            float acc[2][4][4];
#pragma unroll
            for (int mt = 0; mt < 2; ++mt)
#pragma unroll
                for (int nt = 0; nt < 4; ++nt)
#pragma unroll
                    for (int q = 0; q < 4; ++q) acc[mt][nt][q] = 0.f;

#pragma unroll
            for (int k = 0; k < 9; ++k) {
                unsigned a0[4], a1[4], bp0[4], bp1[4];
                ldsm_x4(a0, aAleftU + (unsigned)(k * 32));
                ldsm_x4(a1, aAleftU + (unsigned)(16 * ASTR * 2 + k * 32));
                ldsm_x4(bp0, aBU + (unsigned)(k * 32));
                ldsm_x4(bp1, aBU + (unsigned)(16 * BSTR * 2 + k * 32));
                mma16816(acc[0][0], a0, bp0[0], bp0[1]);
                mma16816(acc[0][1], a0, bp0[2], bp0[3]);
                mma16816(acc[0][2], a0, bp1[0], bp1[1]);
                mma16816(acc[0][3], a0, bp1[2], bp1[3]);
                mma16816(acc[1][0], a1, bp0[0], bp0[1]);
                mma16816(acc[1][1], a1, bp0[2], bp0[3]);
                mma16816(acc[1][2], a1, bp1[0], bp1[1]);
                mma16816(acc[1][3], a1, bp1[2], bp1[3]);
            }

            // left-branch epilogue + combine + publish
#pragma unroll
            for (int p = 0; p < 2; ++p) {
#pragma unroll
                for (int nt = 0; nt < 4; ++nt) {
                    float* c1 = acc[p][nt];
                    float rA = __shfl_xor_sync(0xffffffffu, oddt ? c1[0] : c1[2], 1);
                    float rB = __shfl_xor_sync(0xffffffffu, oddt ? c1[1] : c1[3], 1);
                    float pi, pf, pg, po;
                    if (!oddt) { pi = c1[0]; pf = c1[1]; pg = rA;    po = rB; }
                    else       { pi = rA;    pf = rB;    pg = c1[2]; po = c1[3]; }
                    const int ch = chB + nt * 2;
                    const float bv = sBias[512 + ch];
                    const float i1 = sigf(pi + sBias[ch]);
                    const float f1 = sigf(pf + sBias[128 + ch]);
                    const float g1 = tnhf(pg + sBias[256 + ch]);
                    const float o1 = sigf(po + sBias[384 + ch]);
                    const float cn1 = f1 * cleft[p][nt] + i1 * g1;
                    const float h1  = o1 * tnhf(cn1);

                    const float ct = ws0 * cc[p][nt]  + ws1 * cn1 + bv;
                    const float ht = ws0 * h0s[p][nt] + ws1 * h1  + bv;

                    cleft[p][nt] = ct;
                    const int bb = bbB + p * 16;
                    sA[(32 + (nxt << 5) + bb) * ASTR + ch] = __float2half(ht);
                }
            }
        }

        // ---- publish c: thread-packed, fully coalesced ----
        *reinterpret_cast<float4*>(g_cbuf + rowoff + (tid << 2)) =
            make_float4(cleft[0][0], cleft[0][1], cleft[0][2], cleft[0][3]);
        *reinterpret_cast<float4*>(g_cbuf + rowoff + 2048 + (tid << 2)) =
            make_float4(cleft[1][0], cleft[1][1], cleft[1][2], cleft[1][3]);

        __syncthreads();   // S3: all epilogue h writes to sA visible

        // ---- publish h: coalesced copy of the new left buffer (canonical layout) ----
        *reinterpret_cast<uint4*>(g_hbuf + rowoff + sx_b * 128 + sx_ci * 8) =
            *reinterpret_cast<const uint4*>(sA + (32 + (nxt << 5) + sx_b) * ASTR + sx_ci * 8);

        __syncthreads();   // S4: all global writes done before release
        if (tid == 0) st_rel(&g_progress[bid], (unsigned)(w + 1));
    }

    // ---- output epilogue: transpose f16 row history -> coalesced fp32 stores ----
    // out[d][ch][b][ph][pw] = h[r][w][b][ch], w = fx ? 127-pw : pw
    __half* tile = reinterpret_cast<__half*>(smem);   // reuse sB region (~35 KB)
    float* outp = out + (size_t)d * Oc * Bsz * Hh * Ww;
    __syncthreads();
#pragma unroll 1
    for (int b = 0; b < Bsz; ++b) {
#pragma unroll 1
        for (int idx = tid; idx < 128 * 64; idx += THREADS) {   // u32 units: 128 w x 64
            int wq = idx >> 6, s = idx & 63;
            unsigned v = *reinterpret_cast<const unsigned*>(
                g_hbuf + ((size_t)bid * Ww + wq) * (Bsz * Oc) + b * Oc + s * 2);
            *reinterpret_cast<unsigned*>(tile + wq * TTS + s * 2) = v;
        }
        __syncthreads();
#pragma unroll 1
        for (int idx = tid; idx < 128 * 128; idx += THREADS) {
            int ch = idx >> 7, pw = idx & 127;
            int ww = fx ? (127 - pw) : pw;
            outp[(((size_t)ch * Bsz + b) * Hh + ph) * Ww + pw] =
                __half2float(tile[ww * TTS + ch]);
        }
        __syncthreads();
    }
}

// ---------------- launch ----------------
extern "C" void kernel_launch(void* const* d_in, const int* in_sizes, int n_in,
                              void* d_out, int out_size)
{
    const float* x     = (const float*)d_in[0];
    const float* w_ii  = (const float*)d_in[1];
    const float* w_hi  = (const float*)d_in[2];
    const float* b_i   = (const float*)d_in[3];
    const float* w_if  = (const float*)d_in[4];
    const float* w_hf  = (const float*)d_in[5];
    const float* b_f   = (const float*)d_in[6];
    const float* w_ig  = (const float*)d_in[7];
    const float* w_hg  = (const float*)d_in[8];
    const float* b_g   = (const float*)d_in[9];
    const float* w_io  = (const float*)d_in[10];
    const float* w_ho  = (const float*)d_in[11];
    const float* b_o   = (const float*)d_in[12];
    const float* wsum  = (const float*)d_in[13];
    const float* biasv = (const float*)d_in[14];
    float* out = (float*)d_out;

    cudaFuncSetAttribute(mdlstm_kernel,
                         cudaFuncAttributeMaxDynamicSharedMemorySize, SMEM_TOTAL);

    init_progress_kernel<<<1, 128>>>();
    mdlstm_kernel<<<128, THREADS, SMEM_TOTAL>>>(
        x, w_ii, w_hi, b_i, w_if, w_hf, b_f, w_ig, w_hg, b_g,
        w_io, w_ho, b_o, wsum, biasv, out);
}

// round 8
// speedup vs baseline: 1.9581x; 1.0018x over previous
#include <cuda_runtime.h>
#include <cuda_fp16.h>
#include <cstddef>
#include <cstdint>

// ---------------- problem constants ----------------
#define Bsz   32
#define CINc  16
#define Hh    32
#define Ww    128
#define Oc    128
#define NTOT  512          // 128 channels x 4 gates, interleaved n = ch*4 + gate
#define ASTR  168          // padded half-stride (conflict-free for LDSM rows)
#define BSTR  168
#define THREADS 512

// ---------------- shared memory layout (bytes) ----------------
// A region rows: 0-31 = top (h_top only, cols 0-127),
//                32-63 = left buf0, 64-95 = left buf1 (h cols 0-127 | x cols 128-143)
#define OFF_B     0
#define SZ_B      (NTOT * BSTR * 2)            // 172032
#define OFF_A     (OFF_B + SZ_B)               // 172032
#define SZ_A      (96 * ASTR * 2)              // 32256
#define OFF_BIAS  (OFF_A + SZ_A)               // 204288
#define SZ_BIAS   (5 * Oc * 4)                 // 2560
#define SMEM_TOTAL (OFF_BIAS + SZ_BIAS)        // 206848

// transpose tile stride (halves); 69 words odd -> conflict-free strided reads
#define TTS 138

// ---------------- global scratch ----------------
// g_hbuf: canonical [bid][w][b][ch]   (A-operand staging + output reconstruction)
// g_cbuf: thread-packed [bid][w][p*2048 + tid*4 + nt]  (c handoff, tid-symmetric)
__device__ __align__(256) __half  g_hbuf[(size_t)128 * 128 * 32 * 128];
__device__ __align__(256) float   g_cbuf[(size_t)128 * 128 * 32 * 128];
__device__ unsigned               g_progress[128];

// ---------------- helpers ----------------
__device__ __forceinline__ float tnhf(float x) {
    float y;
    asm("tanh.approx.f32 %0, %1;" : "=f"(y) : "f"(x));
    return y;
}
__device__ __forceinline__ float sigf(float x) {
    return fmaf(tnhf(0.5f * x), 0.5f, 0.5f);
}
__device__ __forceinline__ unsigned ld_acq(const unsigned* p) {
    unsigned v;
    asm volatile("ld.acquire.gpu.global.b32 %0, [%1];" : "=r"(v) : "l"(p));
    return v;
}
__device__ __forceinline__ void st_rel(unsigned* p, unsigned v) {
    asm volatile("st.release.gpu.global.b32 [%0], %1;" :: "l"(p), "r"(v) : "memory");
}
__device__ __forceinline__ void mma16816(float* c, const unsigned* a, unsigned b0, unsigned b1) {
    asm volatile(
        "mma.sync.aligned.m16n8k16.row.col.f32.f16.f16.f32 "
        "{%0,%1,%2,%3}, {%4,%5,%6,%7}, {%8,%9}, {%0,%1,%2,%3};"
        : "+f"(c[0]), "+f"(c[1]), "+f"(c[2]), "+f"(c[3])
        : "r"(a[0]), "r"(a[1]), "r"(a[2]), "r"(a[3]), "r"(b0), "r"(b1));
}
__device__ __forceinline__ void ldsm_x4(unsigned* r, unsigned addr) {
    asm volatile(
        "ldmatrix.sync.aligned.m8n8.x4.shared.b16 {%0,%1,%2,%3}, [%4];"
        : "=r"(r[0]), "=r"(r[1]), "=r"(r[2]), "=r"(r[3]) : "r"(addr));
}

__global__ void init_progress_kernel() {
    if (threadIdx.x < 128) g_progress[threadIdx.x] = 0u;
}

// ---------------- main persistent kernel: one CTA per (direction, row) ----------------
__global__ void __launch_bounds__(THREADS, 1) mdlstm_kernel(
    const float* __restrict__ x,
    const float* __restrict__ w_ii, const float* __restrict__ w_hi, const float* __restrict__ b_i,
    const float* __restrict__ w_if, const float* __restrict__ w_hf, const float* __restrict__ b_f,
    const float* __restrict__ w_ig, const float* __restrict__ w_hg, const float* __restrict__ b_g,
    const float* __restrict__ w_io, const float* __restrict__ w_ho, const float* __restrict__ b_o,
    const float* __restrict__ wsum, const float* __restrict__ biasv,
    float* __restrict__ out)
{
    extern __shared__ char smem[];
    __half* sB    = reinterpret_cast<__half*>(smem + OFF_B);
    __half* sA    = reinterpret_cast<__half*>(smem + OFF_A);
    float*  sBias = reinterpret_cast<float*>(smem + OFF_BIAS);

    const int tid  = threadIdx.x;
    const int lane = tid & 31;
    const int wid  = tid >> 5;          // 0..15
    const int bid  = blockIdx.x;
    const int d    = bid >> 5;
    const int r    = bid & 31;
    const bool fx  = (d & 1) != 0;
    const bool fy  = (d & 2) != 0;
    const int  ph  = fy ? (Hh - 1 - r) : r;

    // ---- stage weights: sB[n][k], n = ch*4 + gate, k = 0..127 (Wh) | 128..143 (Wi) ----
    {
        const float* whArr[4] = {w_hi, w_hf, w_hg, w_ho};
        const float* wiArr[4] = {w_ii, w_if, w_ig, w_io};
        for (int gate = 0; gate < 4; ++gate) {
            const float* wh = whArr[gate] + (size_t)d * Oc * Oc;
            for (int idx = tid; idx < Oc * Oc; idx += THREADS) {
                int ch = idx >> 7, k = idx & 127;
                sB[(ch * 4 + gate) * BSTR + k] = __float2half(wh[idx]);
            }
            const float* wi = wiArr[gate] + (size_t)d * Oc * CINc;
            for (int idx = tid; idx < Oc * CINc; idx += THREADS) {
                int ch = idx >> 4, k = idx & 15;
                sB[(ch * 4 + gate) * BSTR + 128 + k] = __float2half(wi[idx]);
            }
        }
        const float* bArr[4] = {b_i, b_f, b_g, b_o};
        sBias[tid] = bArr[tid >> 7][(size_t)d * Oc + (tid & 127)];
        if (tid < 128) sBias[512 + tid] = biasv[(size_t)d * Oc + tid];
        // zero h columns of left buf0 (read at w=0)
        for (int idx = tid; idx < 32 * 128; idx += THREADS) {
            int b = idx >> 7, c = idx & 127;
            sA[(32 + b) * ASTR + c] = __float2half(0.f);
        }
        if (r == 0) {   // h_top = 0 forever for the first row
            for (int idx = tid; idx < 32 * 128; idx += THREADS) {
                int b = idx >> 7, c = idx & 127;
                sA[b * ASTR + c] = __float2half(0.f);
            }
        }
    }
    const float ws0 = wsum[d * 2 + 0];
    const float ws1 = wsum[d * 2 + 1];

    const int g = lane >> 2, t = lane & 3;
    const bool oddt = (t & 1) != 0;

    // per-thread epilogue ownership
    const int chB = (wid << 3) + (t >> 1);          // + nt*2
    const int bbB = g + (oddt ? 8 : 0);             // + p*16
    const int sx_b = tid >> 4, sx_ci = tid & 15;    // x / h_top / copy staging mapping
    const int n0 = wid << 5;                        // warp's 32 n-cols

    // ldmatrix per-lane address roles
    const unsigned sAu = (unsigned)__cvta_generic_to_shared(sA);
    const unsigned sBu = (unsigned)__cvta_generic_to_shared(sB);
    const int aro  = (lane & 7) + ((lane >> 3) & 1) * 8;   // row within 16
    const int ako  = (lane >> 4) * 8;                      // k-half offset
    const unsigned aAtopU   = sAu + (unsigned)((aro * ASTR + ako) * 2);
    const unsigned aAleftU0 = sAu + (unsigned)(((32 + aro) * ASTR + ako) * 2);
    const unsigned aBU      = sBu + (unsigned)(((n0 + ((lane >> 4) & 1) * 8 + (lane & 7)) * BSTR
                                                + ((lane >> 3) & 1) * 8) * 2);

    float cleft[2][4];                               // c_left lives in registers
#pragma unroll
    for (int p = 0; p < 2; ++p)
#pragma unroll
        for (int nt = 0; nt < 4; ++nt) cleft[p][nt] = 0.f;

    unsigned avail = 0;                              // cached producer progress
    const float* xrow = x + (size_t)tid * (Hh * Ww) + (size_t)ph * Ww;
    const int xm = fx ? 3 : 0;                       // quad-index flip mask

    // prologue: x quad for e=0..3, stage x(0) into buf0 x-cols
    float4 xq = *reinterpret_cast<const float4*>(xrow + (fx ? 124 : 0));
    {
        const int e = 0 ^ xm;
        float s01 = (e & 1) ? xq.y : xq.x;
        float s23 = (e & 1) ? xq.w : xq.z;
        sA[(32 + sx_b) * ASTR + 128 + sx_ci] = __float2half((e & 2) ? s23 : s01);
    }
    __syncthreads();

#pragma unroll 1
    for (int w = 0; w < Ww; ++w) {
        const int cur = w & 1, nxt = cur ^ 1;
        const size_t rowoff  = ((size_t)bid * Ww + w) * (Bsz * Oc);
        const size_t topoff  = rowoff - (size_t)Ww * (Bsz * Oc);
        const size_t prevoff = rowoff - (size_t)(Bsz * Oc);

        // ---- A: poll producer, then prefetch h_top + c_top into registers ----
        uint4 htop_v = make_uint4(0u, 0u, 0u, 0u);
        float ctop_r[2][4];
        if (r > 0) {
            if (avail <= (unsigned)w) {
                avail = ld_acq(&g_progress[bid - 1]);
                while (avail <= (unsigned)w) { __nanosleep(32); avail = ld_acq(&g_progress[bid - 1]); }
            }
            htop_v = *reinterpret_cast<const uint4*>(g_hbuf + topoff + (size_t)tid * 8);
            float4 q0 = *reinterpret_cast<const float4*>(g_cbuf + topoff + (tid << 2));
            float4 q1 = *reinterpret_cast<const float4*>(g_cbuf + topoff + 2048 + (tid << 2));
            ctop_r[0][0] = q0.x; ctop_r[0][1] = q0.y; ctop_r[0][2] = q0.z; ctop_r[0][3] = q0.w;
            ctop_r[1][0] = q1.x; ctop_r[1][1] = q1.y; ctop_r[1][2] = q1.z; ctop_r[1][3] = q1.w;
        } else {
#pragma unroll
            for (int p = 0; p < 2; ++p)
#pragma unroll
                for (int nt = 0; nt < 4; ++nt) ctop_r[p][nt] = 0.f;
        }
        __syncthreads();   // S_A: prev-step epilogue writes (h, x in cur buffer) visible

        // ---- C/D: publish h(w-1) (coalesced copy) + release ----
        if (w > 0) {
            *reinterpret_cast<uint4*>(g_hbuf + prevoff + (size_t)sx_b * 128 + sx_ci * 8) =
                *reinterpret_cast<const uint4*>(sA + (32 + (cur << 5) + sx_b) * ASTR + sx_ci * 8);
        }
        __syncthreads();   // S_copy
        if (w > 0 && tid == 0) st_rel(&g_progress[bid], (unsigned)w);

        const unsigned aAleftU = aAleftU0 + (unsigned)(cur * (32 * ASTR * 2));

        // ================= pass L: LEFT branch (cur buffer; k=8 = x cols) =================
        float ctp[2][4], htp[2][4];
        {
            float acc[2][4][4];
#pragma unroll
            for (int mt = 0; mt < 2; ++mt)
#pragma unroll
                for (int nt = 0; nt < 4; ++nt)
#pragma unroll
                    for (int q = 0; q < 4; ++q) acc[mt][nt][q] = 0.f;

#pragma unroll
            for (int k = 0; k < 9; ++k) {
                unsigned a0[4], a1[4], bp0[4], bp1[4];
                ldsm_x4(a0, aAleftU + (unsigned)(k * 32));
                ldsm_x4(a1, aAleftU + (unsigned)(16 * ASTR * 2 + k * 32));
                ldsm_x4(bp0, aBU + (unsigned)(k * 32));
                ldsm_x4(bp1, aBU + (unsigned)(16 * BSTR * 2 + k * 32));
                mma16816(acc[0][0], a0, bp0[0], bp0[1]);
                mma16816(acc[0][1], a0, bp0[2], bp0[3]);
                mma16816(acc[0][2], a0, bp1[0], bp1[1]);
                mma16816(acc[0][3], a0, bp1[2], bp1[3]);
                mma16816(acc[1][0], a1, bp0[0], bp0[1]);
                mma16816(acc[1][1], a1, bp0[2], bp0[3]);
                mma16816(acc[1][2], a1, bp1[0], bp1[1]);
                mma16816(acc[1][3], a1, bp1[2], bp1[3]);
            }

            // left epilogue -> partial combine held in regs
#pragma unroll
            for (int p = 0; p < 2; ++p) {
#pragma unroll
                for (int nt = 0; nt < 4; ++nt) {
                    float* c1 = acc[p][nt];
                    float rA = __shfl_xor_sync(0xffffffffu, oddt ? c1[0] : c1[2], 1);
                    float rB = __shfl_xor_sync(0xffffffffu, oddt ? c1[1] : c1[3], 1);
                    float pi, pf, pg, po;
                    if (!oddt) { pi = c1[0]; pf = c1[1]; pg = rA;    po = rB; }
                    else       { pi = rA;    pf = rB;    pg = c1[2]; po = c1[3]; }
                    const int ch = chB + nt * 2;
                    const float i1 = sigf(pi + sBias[ch]);
                    const float f1 = sigf(pf + sBias[128 + ch]);
                    const float g1 = tnhf(pg + sBias[256 + ch]);
                    const float o1 = sigf(po + sBias[384 + ch]);
                    const float cn1 = f1 * cleft[p][nt] + i1 * g1;
                    const float h1  = o1 * tnhf(cn1);
                    const float bv  = sBias[512 + ch];
                    ctp[p][nt] = fmaf(ws1, cn1, bv);
                    htp[p][nt] = fmaf(ws1, h1, bv);
                }
            }
        }

        // ---- F: stage h_top (from prefetched regs) into top rows ----
        if (r > 0)
            *reinterpret_cast<uint4*>(sA + sx_b * ASTR + sx_ci * 8) = htop_v;
        __syncthreads();   // S_top

        // ================= pass T: TOP branch (top rows; k=8 from cur-left x cols) =========
        {
            float acc[2][4][4];
#pragma unroll
            for (int mt = 0; mt < 2; ++mt)
#pragma unroll
                for (int nt = 0; nt < 4; ++nt)
#pragma unroll
                    for (int q = 0; q < 4; ++q) acc[mt][nt][q] = 0.f;

#pragma unroll
            for (int k = 0; k < 9; ++k) {
                const unsigned ab = (k < 8) ? (aAtopU + (unsigned)(k * 32))
                                            : (aAleftU + (unsigned)(8 * 32));
                unsigned a0[4], a1[4], bp0[4], bp1[4];
                ldsm_x4(a0, ab);
                ldsm_x4(a1, ab + (unsigned)(16 * ASTR * 2));
                ldsm_x4(bp0, aBU + (unsigned)(k * 32));
                ldsm_x4(bp1, aBU + (unsigned)(16 * BSTR * 2 + k * 32));
                mma16816(acc[0][0], a0, bp0[0], bp0[1]);
                mma16816(acc[0][1], a0, bp0[2], bp0[3]);
                mma16816(acc[0][2], a0, bp1[0], bp1[1]);
                mma16816(acc[0][3], a0, bp1[2], bp1[3]);
                mma16816(acc[1][0], a1, bp0[0], bp0[1]);
                mma16816(acc[1][1], a1, bp0[2], bp0[3]);
                mma16816(acc[1][2], a1, bp1[0], bp1[1]);
                mma16816(acc[1][3], a1, bp1[2], bp1[3]);
            }

            // top epilogue + combine + publish
#pragma unroll
            for (int p = 0; p < 2; ++p) {
#pragma unroll
                for (int nt = 0; nt < 4; ++nt) {
                    float* c0 = acc[p][nt];
                    float rA = __shfl_xor_sync(0xffffffffu, oddt ? c0[0] : c0[2], 1);
                    float rB = __shfl_xor_sync(0xffffffffu, oddt ? c0[1] : c0[3], 1);
                    float pi, pf, pg, po;
                    if (!oddt) { pi = c0[0]; pf = c0[1]; pg = rA;    po = rB; }
                    else       { pi = rA;    pf = rB;    pg = c0[2]; po = c0[3]; }
                    const int ch = chB + nt * 2;
                    const float i0 = sigf(pi + sBias[ch]);
                    const float f0 = sigf(pf + sBias[128 + ch]);
                    const float g0 = tnhf(pg + sBias[256 + ch]);
                    const float o0 = sigf(po + sBias[384 + ch]);
                    const float cn0 = f0 * ctop_r[p][nt] + i0 * g0;
                    const float h0  = o0 * tnhf(cn0);

                    const float ct = fmaf(ws0, cn0, ctp[p][nt]);
                    const float ht = fmaf(ws0, h0,  htp[p][nt]);

                    cleft[p][nt] = ct;
                    const int bb = bbB + p * 16;
                    sA[(32 + (nxt << 5) + bb) * ASTR + ch] = __float2half(ht);
                }
            }
        }

        // ---- I: publish c (coalesced, packed); stage x(w+1) into next buffer ----
        *reinterpret_cast<float4*>(g_cbuf + rowoff + (tid << 2)) =
            make_float4(cleft[0][0], cleft[0][1], cleft[0][2], cleft[0][3]);
        *reinterpret_cast<float4*>(g_cbuf + rowoff + 2048 + (tid << 2)) =
            make_float4(cleft[1][0], cleft[1][1], cleft[1][2], cleft[1][3]);

        if (w + 1 < Ww) {
            const int e = w + 1;
            if ((e & 3) == 0)
                xq = *reinterpret_cast<const float4*>(xrow + (fx ? (124 - e) : e));
            const int ei = (e & 3) ^ xm;
            float s01 = (ei & 1) ? xq.y : xq.x;
            float s23 = (ei & 1) ? xq.w : xq.z;
            sA[(32 + (nxt << 5) + sx_b) * ASTR + 128 + sx_ci] =
                __float2half((ei & 2) ? s23 : s01);
        }
    }

    // ---- post-loop: publish h(127) and final release ----
    __syncthreads();
    {
        const size_t lastoff = ((size_t)bid * Ww + (Ww - 1)) * (Bsz * Oc);
        const int fbuf = Ww & 1;   // nxt of w=127
        *reinterpret_cast<uint4*>(g_hbuf + lastoff + (size_t)sx_b * 128 + sx_ci * 8) =
            *reinterpret_cast<const uint4*>(sA + (32 + (fbuf << 5) + sx_b) * ASTR + sx_ci * 8);
    }
    __syncthreads();
    if (tid == 0) st_rel(&g_progress[bid], (unsigned)Ww);

    // ---- output epilogue: transpose f16 row history -> coalesced fp32 stores ----
    // out[d][ch][b][ph][pw] = h[r][w][b][ch], w = fx ? 127-pw : pw
    __half* tile = reinterpret_cast<__half*>(smem);   // reuse sB region (~35 KB)
    float* outp = out + (size_t)d * Oc * Bsz * Hh * Ww;
    __syncthreads();
#pragma unroll 1
    for (int b = 0; b < Bsz; ++b) {
#pragma unroll 1
        for (int idx = tid; idx < 128 * 64; idx += THREADS) {   // u32 units: 128 w x 64
            int wq = idx >> 6, s = idx & 63;
            unsigned v = *reinterpret_cast<const unsigned*>(
                g_hbuf + ((size_t)bid * Ww + wq) * (Bsz * Oc) + b * Oc + s * 2);
            *reinterpret_cast<unsigned*>(tile + wq * TTS + s * 2) = v;
        }
        __syncthreads();
#pragma unroll 1
        for (int idx = tid; idx < 128 * 128; idx += THREADS) {
            int ch = idx >> 7, pw = idx & 127;
            int ww = fx ? (127 - pw) : pw;
            outp[(((size_t)ch * Bsz + b) * Hh + ph) * Ww + pw] =
                __half2float(tile[ww * TTS + ch]);
        }
        __syncthreads();
    }
}

// ---------------- launch ----------------
extern "C" void kernel_launch(void* const* d_in, const int* in_sizes, int n_in,
                              void* d_out, int out_size)
{
    const float* x     = (const float*)d_in[0];
    const float* w_ii  = (const float*)d_in[1];
    const float* w_hi  = (const float*)d_in[2];
    const float* b_i   = (const float*)d_in[3];
    const float* w_if  = (const float*)d_in[4];
    const float* w_hf  = (const float*)d_in[5];
    const float* b_f   = (const float*)d_in[6];
    const float* w_ig  = (const float*)d_in[7];
    const float* w_hg  = (const float*)d_in[8];
    const float* b_g   = (const float*)d_in[9];
    const float* w_io  = (const float*)d_in[10];
    const float* w_ho  = (const float*)d_in[11];
    const float* b_o   = (const float*)d_in[12];
    const float* wsum  = (const float*)d_in[13];
    const float* biasv = (const float*)d_in[14];
    float* out = (float*)d_out;

    cudaFuncSetAttribute(mdlstm_kernel,
                         cudaFuncAttributeMaxDynamicSharedMemorySize, SMEM_TOTAL);

    init_progress_kernel<<<1, 128>>>();
    mdlstm_kernel<<<128, THREADS, SMEM_TOTAL>>>(
        x, w_ii, w_hi, b_i, w_if, w_hf, b_f, w_ig, w_hg, b_g,
        w_io, w_ho, b_o, wsum, biasv, out);
}